// round 17
// baseline (speedup 1.0000x reference)
#include <cuda_runtime.h>
#include <cstdint>

#define NB 8
#define NN 2048
#define DD 128

// Scratch (static device globals — no runtime allocation)
__device__ float g_hn[NB * NN * DD];   // normalized h, row-major [B][N][D]
__device__ float g_ht[NB * DD * NN];   // h (unnormalized), TRANSPOSED [B][D][N]

__device__ __forceinline__ float to_tf32(float x) {
    float r;
    asm("cvt.rna.tf32.f32 %0, %1;" : "=f"(r) : "f"(x));
    return r;
}
__device__ __forceinline__ unsigned fbits(float x) { return __float_as_uint(x); }

// D += A(16x8, tf32 row) * B(8x8, tf32 col), fp32 accumulate
__device__ __forceinline__ void mma8(float c[4], const unsigned a[4], unsigned b0, unsigned b1) {
    asm volatile(
        "mma.sync.aligned.m16n8k8.row.col.f32.tf32.tf32.f32 "
        "{%0,%1,%2,%3}, {%4,%5,%6,%7}, {%8,%9}, {%0,%1,%2,%3};\n"
        : "+f"(c[0]), "+f"(c[1]), "+f"(c[2]), "+f"(c[3])
        : "r"(a[0]), "r"(a[1]), "r"(a[2]), "r"(a[3]), "r"(b0), "r"(b1));
}

__device__ __forceinline__ void cp16(float* dst_smem, const float* src) {
    unsigned d = (unsigned)__cvta_generic_to_shared(dst_smem);
    asm volatile("cp.async.cg.shared.global [%0], [%1], 16;" :: "r"(d), "l"(src));
}
#define CP_COMMIT() asm volatile("cp.async.commit_group;")
#define CP_WAIT0()  asm volatile("cp.async.wait_group 0;")

// ---------------------------------------------------------------------------
// Phase 1 (UNCHANGED, verified): h = x @ W^T + b ; writes g_hn, g_ht.
// Grid: 128 CTAs x 256 thr.
// ---------------------------------------------------------------------------
__global__ __launch_bounds__(256, 1)
void linear_norm_kernel(const float* __restrict__ x, const float* __restrict__ W,
                        const float* __restrict__ bias) {
    extern __shared__ float sm[];
    float* sX = sm;              // [128][132]
    float* sW = sm + 128 * 132;  // [128][132]
    const int tid = threadIdx.x, lane = tid & 31, wid = tid >> 5;
    const int g = lane >> 2, q = lane & 3, wm = wid * 16;
    const int r0 = blockIdx.x * 128;
    const int b  = r0 >> 11;
    const int n0 = r0 & (NN - 1);

    for (int i = tid; i < 128 * 32; i += 256) {
        int r = i >> 5, c = (i & 31) * 4;
        float4 v = *(const float4*)(x + (size_t)(r0 + r) * 128 + c);
        float* d = sX + r * 132 + c;
        d[0] = to_tf32(v.x); d[1] = to_tf32(v.y); d[2] = to_tf32(v.z); d[3] = to_tf32(v.w);
        float4 w = *(const float4*)(W + (size_t)r * 128 + c);
        float* dw = sW + r * 132 + c;
        dw[0] = to_tf32(w.x); dw[1] = to_tf32(w.y); dw[2] = to_tf32(w.z); dw[3] = to_tf32(w.w);
    }
    __syncthreads();

    float acc[16][4];
#pragma unroll
    for (int nf = 0; nf < 16; nf++) { acc[nf][0] = acc[nf][1] = acc[nf][2] = acc[nf][3] = 0.f; }

#pragma unroll
    for (int ks = 0; ks < 16; ks++) {
        const int k0 = ks * 8;
        const float* ar = sX + (wm + g) * 132;
        unsigned a[4];
        a[0] = fbits(ar[k0 + q]);             a[1] = fbits(ar[8 * 132 + k0 + q]);
        a[2] = fbits(ar[k0 + q + 4]);         a[3] = fbits(ar[8 * 132 + k0 + q + 4]);
#pragma unroll
        for (int nf = 0; nf < 16; nf++) {
            const float* br = sW + (nf * 8 + g) * 132;
            mma8(acc[nf], a, fbits(br[k0 + q]), fbits(br[k0 + q + 4]));
        }
    }

    float s0 = 0.f, s1 = 0.f;
#pragma unroll
    for (int nf = 0; nf < 16; nf++) {
        int c = nf * 8 + 2 * q;
        float b0 = bias[c], b1 = bias[c + 1];
        acc[nf][0] += b0; acc[nf][1] += b1; acc[nf][2] += b0; acc[nf][3] += b1;
        s0 += acc[nf][0] * acc[nf][0] + acc[nf][1] * acc[nf][1];
        s1 += acc[nf][2] * acc[nf][2] + acc[nf][3] * acc[nf][3];
    }
    s0 += __shfl_xor_sync(0xffffffffu, s0, 1);
    s0 += __shfl_xor_sync(0xffffffffu, s0, 2);
    s1 += __shfl_xor_sync(0xffffffffu, s1, 1);
    s1 += __shfl_xor_sync(0xffffffffu, s1, 2);
    const float inv0 = 1.f / fmaxf(sqrtf(s0), 1e-12f);
    const float inv1 = 1.f / fmaxf(sqrtf(s1), 1e-12f);

    const size_t row0 = (size_t)(r0 + wm + g) * 128;
    const size_t row1 = (size_t)(r0 + wm + g + 8) * 128;
#pragma unroll
    for (int nf = 0; nf < 16; nf++) {
        int c = nf * 8 + 2 * q;
        *(float2*)(g_hn + row0 + c) = make_float2(to_tf32(acc[nf][0] * inv0), to_tf32(acc[nf][1] * inv0));
        *(float2*)(g_hn + row1 + c) = make_float2(to_tf32(acc[nf][2] * inv1), to_tf32(acc[nf][3] * inv1));
    }

    __syncthreads();
    float* sT = sm;
#pragma unroll
    for (int nf = 0; nf < 16; nf++) {
        int c = nf * 8 + 2 * q;
        sT[(c + 0) * 132 + wm + g]     = to_tf32(acc[nf][0]);
        sT[(c + 1) * 132 + wm + g]     = to_tf32(acc[nf][1]);
        sT[(c + 0) * 132 + wm + g + 8] = to_tf32(acc[nf][2]);
        sT[(c + 1) * 132 + wm + g + 8] = to_tf32(acc[nf][3]);
    }
    __syncthreads();
    float* dstb = g_ht + (size_t)b * DD * NN;
    for (int i = tid; i < 128 * 32; i += 256) {
        int d = i >> 5, c4 = (i & 31) * 4;
        float4 v = *(const float4*)(sT + d * 132 + c4);
        *(float4*)(dstb + (size_t)d * NN + n0 + c4) = v;
    }
}

// ---------------------------------------------------------------------------
// Phase 2 (REWORKED for occupancy): 512 threads, 16 warps.
// GEMM1 k-split: warp kh=wid>>3 computes partial S over K-half; partials are
// exchanged via sP with symmetric column-split gating (warp gates cols
// [kh*32, kh*32+32) of its 16 rows). GEMM2: m16 x n64 per warp (n-half = kh).
// Regs/thread ~= aF 32 + s 32 + acc 32. smem 202 KB. Grid (16, 8).
// ---------------------------------------------------------------------------
__global__ __launch_bounds__(512, 1)
void aggregate_kernel(const float* __restrict__ ew, float* __restrict__ out) {
    extern __shared__ float sm[];
    float* sHN0 = sm;                    // [64][132]  hn q-tile  (GEMM1 B)
    float* sHN1 = sHN0 + 64 * 132;
    float* sHT0 = sHN1 + 64 * 132;       // [128 d][68] h q-tile  (GEMM2 B)
    float* sHT1 = sHT0 + 128 * 68;
    float* sS   = sHT1 + 128 * 68;       // [128][68]  final gated S (GEMM2 A)
    float* sP   = sS   + 128 * 68;       // [128][68]  cross-k-half partials

    const int tid = threadIdx.x, lane = tid & 31, wid = tid >> 5;
    const int g = lane >> 2, q = lane & 3;
    const int wlocal = wid & 7;          // m-position (8 x 16 rows = 128)
    const int kh     = wid >> 3;         // 0/1: GEMM1 k-half, gating col-half, GEMM2 n-half
    const int wm  = wlocal * 16;
    const int nc2 = kh * 64;             // GEMM2 n-offset
    const int gc  = kh * 32;             // gating: own column half
    const int oc  = 32 - gc;             // gating: other column half
    const int m0 = blockIdx.x * 128;
    const int b = blockIdx.y;
    const float* hn = g_hn + (size_t)b * NN * DD;
    const float* ht = g_ht + (size_t)b * DD * NN;

    // --- cp.async tile 0 ---
    {
#pragma unroll
        for (int t = 0; t < 4; t++) {                  // sHN: 64 x 32 chunks
            int idx = tid + t * 512;
            int r = idx >> 5, ck = (idx & 31) * 4;
            cp16(sHN0 + r * 132 + ck, hn + (size_t)r * 128 + ck);
        }
#pragma unroll
        for (int t = 0; t < 4; t++) {                  // sHT: 128 x 16 chunks
            int idx = tid + t * 512;
            int d = idx >> 4, ck = (idx & 15) * 4;
            cp16(sHT0 + d * 68 + ck, ht + (size_t)d * NN + ck);
        }
        CP_COMMIT();
    }

    // --- GEMM1 A-fragments: this warp's K-half only (32 regs) ---
    unsigned aF[8][4];
    {
        const float* ar0 = hn + (size_t)(m0 + wm + g) * 128 + kh * 64;
        const float* ar1 = ar0 + 8 * 128;
#pragma unroll
        for (int ks = 0; ks < 8; ks++) {
            int k0 = ks * 8;
            aF[ks][0] = fbits(ar0[k0 + q]);
            aF[ks][1] = fbits(ar1[k0 + q]);
            aF[ks][2] = fbits(ar0[k0 + q + 4]);
            aF[ks][3] = fbits(ar1[k0 + q + 4]);
        }
    }

    float acc[8][4];
#pragma unroll
    for (int nf = 0; nf < 8; nf++) { acc[nf][0] = acc[nf][1] = acc[nf][2] = acc[nf][3] = 0.f; }

    const float* e0base = ew + ((size_t)b * NN + (m0 + wm + g)) * NN;
    const float* e1base = e0base + 8 * NN;
    float*       ssg0 = sS + (wm + g) * 68 + gc;       // own-half gated writes
    float*       ssg1 = sS + (wm + g + 8) * 68 + gc;
    const float* spg0 = sP + (wm + g) * 68 + gc;       // partner partial (my cols)
    const float* spg1 = sP + (wm + g + 8) * 68 + gc;
    float*       spo0 = sP + (wm + g) * 68 + oc;       // my partial (partner cols)
    float*       spo1 = sP + (wm + g + 8) * 68 + oc;
    const float* sr0 = sS + (wm + g) * 68;             // GEMM2 A rows
    const float* sr1 = sS + (wm + g + 8) * 68;

    for (int it = 0; it < 32; it++) {
        const int q0 = it * 64;
        float* bHN = (it & 1) ? sHN1 : sHN0;
        float* bHT = (it & 1) ? sHT1 : sHT0;

        CP_WAIT0();
        __syncthreads();   // tile `it` visible; prev iter's smem reads done

        if (it < 31) {
            float* nHN = (it & 1) ? sHN0 : sHN1;
            float* nHT = (it & 1) ? sHT0 : sHT1;
            const float* srcn = hn + (size_t)(q0 + 64) * 128;
            const float* srct = ht + (q0 + 64);
#pragma unroll
            for (int t = 0; t < 4; t++) {
                int idx = tid + t * 512;
                int r = idx >> 5, ck = (idx & 31) * 4;
                cp16(nHN + r * 132 + ck, srcn + (size_t)r * 128 + ck);
            }
#pragma unroll
            for (int t = 0; t < 4; t++) {
                int idx = tid + t * 512;
                int d = idx >> 4, ck = (idx & 15) * 4;
                cp16(nHT + d * 68 + ck, srct + (size_t)d * NN + ck);
            }
            CP_COMMIT();
            // L2-prefetch next iteration's ew gating lines (non-faulting)
#pragma unroll
            for (int nf4 = 0; nf4 < 4; nf4++) {
                int c = gc + nf4 * 8 + 2 * q;
                asm volatile("prefetch.global.L2 [%0];" :: "l"(e0base + q0 + 64 + c));
                asm volatile("prefetch.global.L2 [%0];" :: "l"(e1base + q0 + 64 + c));
            }
        }

        // GEMM1 (partial over this warp's K-half): S16x64 rows wm..wm+16
        float s[8][4];
#pragma unroll
        for (int nf = 0; nf < 8; nf++) { s[nf][0] = s[nf][1] = s[nf][2] = s[nf][3] = 0.f; }
#pragma unroll
        for (int ks = 0; ks < 8; ks++) {
            const int k0 = kh * 64 + ks * 8;
#pragma unroll
            for (int nf = 0; nf < 8; nf++) {
                const float* br = bHN + (nf * 8 + g) * 132;
                mma8(s[nf], aF[ks], fbits(br[k0 + q]), fbits(br[k0 + q + 4]));
            }
        }

        // publish my partial for the OTHER column half
#pragma unroll
        for (int nf4 = 0; nf4 < 4; nf4++) {
            int nfo = (1 - kh) * 4 + nf4;
            int c = nf4 * 8 + 2 * q;
            *(float2*)(spo0 + c) = make_float2(s[nfo][0], s[nfo][1]);
            *(float2*)(spo1 + c) = make_float2(s[nfo][2], s[nfo][3]);
        }
        __syncthreads();

        // gate own column half: own partial + partner partial, * ew, tf32-round
#pragma unroll
        for (int nf4 = 0; nf4 < 4; nf4++) {
            int nfo = kh * 4 + nf4;
            int c = nf4 * 8 + 2 * q;
            float2 p0 = *(const float2*)(spg0 + c);
            float2 p1 = *(const float2*)(spg1 + c);
            float2 w0 = *(const float2*)(e0base + q0 + gc + c);
            float2 w1 = *(const float2*)(e1base + q0 + gc + c);
            *(float2*)(ssg0 + c) = make_float2(to_tf32((s[nfo][0] + p0.x) * w0.x),
                                               to_tf32((s[nfo][1] + p0.y) * w0.y));
            *(float2*)(ssg1 + c) = make_float2(to_tf32((s[nfo][2] + p1.x) * w1.x),
                                               to_tf32((s[nfo][3] + p1.y) * w1.y));
        }
        __syncthreads();

        // GEMM2: ACC(m16 x n64 per warp) += S @ Hq
#pragma unroll
        for (int ks = 0; ks < 8; ks++) {
            const int k0 = ks * 8;
            unsigned a[4];
            a[0] = fbits(sr0[k0 + q]);
            a[1] = fbits(sr1[k0 + q]);
            a[2] = fbits(sr0[k0 + q + 4]);
            a[3] = fbits(sr1[k0 + q + 4]);
#pragma unroll
            for (int nf = 0; nf < 8; nf++) {
                const float* br = bHT + (nc2 + nf * 8 + g) * 68;
                mma8(acc[nf], a, fbits(br[k0 + q]), fbits(br[k0 + q + 4]));
            }
        }
    }

    // ReLU + store: rows m0+wm+{g, g+8}, cols nc2 + nf*8 + 2q
    float* o0 = out + ((size_t)b * NN + (m0 + wm + g)) * DD;
    float* o1 = o0 + 8 * DD;
#pragma unroll
    for (int nf = 0; nf < 8; nf++) {
        int c = nc2 + nf * 8 + 2 * q;
        *(float2*)(o0 + c) = make_float2(fmaxf(acc[nf][0], 0.f), fmaxf(acc[nf][1], 0.f));
        *(float2*)(o1 + c) = make_float2(fmaxf(acc[nf][2], 0.f), fmaxf(acc[nf][3], 0.f));
    }
}

extern "C" void kernel_launch(void* const* d_in, const int* in_sizes, int n_in,
                              void* d_out, int out_size) {
    const float* x    = (const float*)d_in[0];
    const float* ew   = (const float*)d_in[1];
    const float* W    = (const float*)d_in[2];
    const float* bias = (const float*)d_in[3];
    float* out = (float*)d_out;

    const int smem1 = 2 * 128 * 132 * (int)sizeof(float);                            // 135168
    const int smem2 = (2 * 64 * 132 + 4 * 128 * 68) * (int)sizeof(float);            // 206848
    cudaFuncSetAttribute(linear_norm_kernel, cudaFuncAttributeMaxDynamicSharedMemorySize, smem1);
    cudaFuncSetAttribute(aggregate_kernel, cudaFuncAttributeMaxDynamicSharedMemorySize, smem2);

    linear_norm_kernel<<<128, 256, smem1>>>(x, W, bias);
    dim3 grid2(16, 8);
    aggregate_kernel<<<grid2, 512, smem2>>>(ew, out);
}